// round 1
// baseline (speedup 1.0000x reference)
#include <cuda_runtime.h>
#include <math.h>

#define Bn 16
#define Sn 768
#define Hn 768
#define Tn 128
#define NQn 640
#define DHn 64
#define NHn 12
#define CHn 10

// Scratch (device globals — no cudaMalloc allowed)
__device__ float g_Q[(size_t)Bn * Sn * Hn];
__device__ float g_K[(size_t)Bn * Sn * Hn];
__device__ float g_V[(size_t)Bn * Sn * Hn];
__device__ float g_Vsum[Bn * Hn];

// ---------------------------------------------------------------------------
// C = A @ W^T + bias ; A: [12288, 768] row-major, W: [768, 768] row-major.
// 128x128 tile, BK=8, 256 threads, 8x8 per thread.
// which: 0 -> g_Q, 1 -> g_K, 2 -> g_V
// ---------------------------------------------------------------------------
__global__ __launch_bounds__(256) void gemm_bias_nt(
    const float* __restrict__ A, const float* __restrict__ W,
    const float* __restrict__ bias, int which)
{
    __shared__ float As[8][128];
    __shared__ float Ws[8][128];

    float* C = (which == 0) ? g_Q : (which == 1) ? g_K : g_V;

    const int tid = threadIdx.x;
    const int tx = tid & 15;        // 0..15  (N direction)
    const int ty = tid >> 4;        // 0..15  (M direction)
    const int rowBase = blockIdx.y * 128;
    const int colBase = blockIdx.x * 128;

    const int lrow = tid >> 1;          // 0..127
    const int lk   = (tid & 1) * 4;     // 0 or 4

    const float* Arow = A + (size_t)(rowBase + lrow) * Hn;
    const float* Wrow = W + (size_t)(colBase + lrow) * Hn;

    float acc[8][8];
#pragma unroll
    for (int i = 0; i < 8; i++)
#pragma unroll
        for (int j = 0; j < 8; j++) acc[i][j] = 0.f;

    for (int k0 = 0; k0 < Hn; k0 += 8) {
        float4 av = *(const float4*)(Arow + k0 + lk);
        float4 wv = *(const float4*)(Wrow + k0 + lk);
        __syncthreads();
        As[lk + 0][lrow] = av.x; As[lk + 1][lrow] = av.y;
        As[lk + 2][lrow] = av.z; As[lk + 3][lrow] = av.w;
        Ws[lk + 0][lrow] = wv.x; Ws[lk + 1][lrow] = wv.y;
        Ws[lk + 2][lrow] = wv.z; Ws[lk + 3][lrow] = wv.w;
        __syncthreads();
#pragma unroll
        for (int k = 0; k < 8; k++) {
            float a[8], b[8];
            *(float4*)(a)     = *(const float4*)&As[k][ty * 8];
            *(float4*)(a + 4) = *(const float4*)&As[k][ty * 8 + 4];
            *(float4*)(b)     = *(const float4*)&Ws[k][tx * 8];
            *(float4*)(b + 4) = *(const float4*)&Ws[k][tx * 8 + 4];
#pragma unroll
            for (int i = 0; i < 8; i++)
#pragma unroll
                for (int j = 0; j < 8; j++)
                    acc[i][j] = fmaf(a[i], b[j], acc[i][j]);
        }
    }

#pragma unroll
    for (int i = 0; i < 8; i++) {
        float* Crow = C + (size_t)(rowBase + ty * 8 + i) * Hn + colBase + tx * 8;
#pragma unroll
        for (int j4 = 0; j4 < 2; j4++) {
            float4 v;
            int j = j4 * 4;
            v.x = acc[i][j + 0] + bias[colBase + tx * 8 + j + 0];
            v.y = acc[i][j + 1] + bias[colBase + tx * 8 + j + 1];
            v.z = acc[i][j + 2] + bias[colBase + tx * 8 + j + 2];
            v.w = acc[i][j + 3] + bias[colBase + tx * 8 + j + 3];
            *(float4*)(Crow + j) = v;
        }
    }
}

// ---------------------------------------------------------------------------
// Per-(b, col) sum of V over the first 640 sequence rows.
// ---------------------------------------------------------------------------
__global__ void vsum_kernel()
{
    int b = blockIdx.x;
    int c = threadIdx.x;  // 0..767
    const float* base = g_V + (size_t)b * Sn * Hn + c;
    float acc = 0.f;
    for (int s = 0; s < NQn; s++) acc += base[(size_t)s * Hn];
    g_Vsum[b * Hn + c] = acc;
}

// ---------------------------------------------------------------------------
// Output rows >= 640 are the raw V projection rows.
// ---------------------------------------------------------------------------
__global__ void tail_copy(float* __restrict__ out)
{
    int b = blockIdx.x / Tn;
    int t = blockIdx.x % Tn;
    size_t r = (size_t)b * Sn + NQn + t;
    out[r * Hn + threadIdx.x] = g_V[r * Hn + threadIdx.x];
}

// ---------------------------------------------------------------------------
// Fused attention: one CTA per (chunk, head, batch).
// 64 queries x 192 keys (64 chunk + 128 tail); masked columns folded in via
// exp(-m) * (Vsum640 - Vchunk) correction.
// ---------------------------------------------------------------------------
__global__ __launch_bounds__(256) void attn_kernel(float* __restrict__ out)
{
    extern __shared__ float sm[];
    float* sq  = sm;                    // 64 * 65
    float* sk  = sq + 64 * 65;          // 192 * 65
    float* sv  = sk + 192 * 65;         // 192 * 65
    float* sp  = sv + 192 * 65;         // 64 * 192
    float* sem = sp + 64 * 192;         // 64
    float* sz  = sem + 64;              // 64
    float* sms = sz + 64;               // 64

    const int tid = threadIdx.x;
    const int chunk = blockIdx.x;
    const int h = blockIdx.y;
    const int b = blockIdx.z;

    const size_t rowQ0 = ((size_t)b * Sn + chunk * 64) * Hn + h * DHn;
    // load Q tile (64 x 64)
    for (int idx = tid; idx < 64 * 64; idx += 256) {
        int i = idx >> 6, d = idx & 63;
        sq[i * 65 + d] = g_Q[rowQ0 + (size_t)i * Hn + d];
    }
    // load K, V tiles (192 x 64): j<64 -> chunk keys, j>=64 -> tail keys
    for (int idx = tid; idx < 192 * 64; idx += 256) {
        int j = idx >> 6, d = idx & 63;
        int s = (j < 64) ? (chunk * 64 + j) : (576 + j);  // 640 + (j-64)
        size_t off = ((size_t)b * Sn + s) * Hn + h * DHn + d;
        sk[j * 65 + d] = g_K[off];
        sv[j * 65 + d] = g_V[off];
    }
    __syncthreads();

    const int tx = tid & 15;   // 16 -> j blocks of 12
    const int ty = tid >> 4;   // 16 -> i blocks of 4

    // scores: 4 x 12 per thread
    {
        float acc[4][12];
#pragma unroll
        for (int ii = 0; ii < 4; ii++)
#pragma unroll
            for (int jj = 0; jj < 12; jj++) acc[ii][jj] = 0.f;
        const int i0 = ty * 4, j0 = tx * 12;
        for (int d = 0; d < 64; d++) {
            float a[4], kb[12];
#pragma unroll
            for (int ii = 0; ii < 4; ii++) a[ii] = sq[(i0 + ii) * 65 + d];
#pragma unroll
            for (int jj = 0; jj < 12; jj++) kb[jj] = sk[(j0 + jj) * 65 + d];
#pragma unroll
            for (int ii = 0; ii < 4; ii++)
#pragma unroll
                for (int jj = 0; jj < 12; jj++)
                    acc[ii][jj] = fmaf(a[ii], kb[jj], acc[ii][jj]);
        }
#pragma unroll
        for (int ii = 0; ii < 4; ii++)
#pragma unroll
            for (int jj = 0; jj < 12; jj++)
                sp[(i0 + ii) * 192 + j0 + jj] = acc[ii][jj] * 0.125f;
    }
    __syncthreads();

    // softmax with zero-fill correction (masked score == 0, 576 masked cols)
    if (tid < 64) {
        const int i = tid;
        float m = 0.f;
        for (int j = 0; j < 192; j++) m = fmaxf(m, sp[i * 192 + j]);
        float Z = 0.f;
        for (int j = 0; j < 192; j++) {
            float e = __expf(sp[i * 192 + j] - m);
            sp[i * 192 + j] = e;
            Z += e;
        }
        float em = __expf(-m);
        Z += 576.f * em;
        sem[i] = em;
        sz[i]  = 1.f / Z;
    } else if (tid < 128) {
        // masked-v sum = Vsum(first 640 rows) - chunk-v sum
        const int d = tid - 64;
        float acc = 0.f;
        for (int j = 0; j < 64; j++) acc += sv[j * 65 + d];
        sms[d] = g_Vsum[b * Hn + h * DHn + d] - acc;
    }
    __syncthreads();

    // ctx: 4 x 4 per thread over 192 keys
    {
        float acc[4][4];
#pragma unroll
        for (int ii = 0; ii < 4; ii++)
#pragma unroll
            for (int dd = 0; dd < 4; dd++) acc[ii][dd] = 0.f;
        const int i0 = ty * 4, d0 = tx * 4;
        for (int j = 0; j < 192; j++) {
            float pv[4], vj[4];
#pragma unroll
            for (int ii = 0; ii < 4; ii++) pv[ii] = sp[(i0 + ii) * 192 + j];
#pragma unroll
            for (int dd = 0; dd < 4; dd++) vj[dd] = sv[j * 65 + d0 + dd];
#pragma unroll
            for (int ii = 0; ii < 4; ii++)
#pragma unroll
                for (int dd = 0; dd < 4; dd++)
                    acc[ii][dd] = fmaf(pv[ii], vj[dd], acc[ii][dd]);
        }
#pragma unroll
        for (int ii = 0; ii < 4; ii++) {
            float* orow = out + ((size_t)b * Sn + chunk * 64 + i0 + ii) * Hn + h * DHn + d0;
            float inv = sz[i0 + ii];
            float em  = sem[i0 + ii];
#pragma unroll
            for (int dd = 0; dd < 4; dd++)
                orow[dd] = (acc[ii][dd] + em * sms[d0 + dd]) * inv;
        }
    }
}

// ---------------------------------------------------------------------------
extern "C" void kernel_launch(void* const* d_in, const int* in_sizes, int n_in,
                              void* d_out, int out_size)
{
    const float* hs = (const float*)d_in[0];
    const float* Wq = (const float*)d_in[1];
    const float* bq = (const float*)d_in[2];
    const float* Wk = (const float*)d_in[3];
    const float* bk = (const float*)d_in[4];
    const float* Wv = (const float*)d_in[5];
    const float* bv = (const float*)d_in[6];
    float* out = (float*)d_out;

    dim3 ggrid(Hn / 128, (Bn * Sn) / 128);   // (6, 96)
    gemm_bias_nt<<<ggrid, 256>>>(hs, Wq, bq, 0);
    gemm_bias_nt<<<ggrid, 256>>>(hs, Wk, bk, 1);
    gemm_bias_nt<<<ggrid, 256>>>(hs, Wv, bv, 2);

    vsum_kernel<<<Bn, Hn>>>();
    tail_copy<<<Bn * Tn, Hn>>>(out);

    const size_t smem = (size_t)(64 * 65 + 2 * 192 * 65 + 64 * 192 + 3 * 64) * sizeof(float);
    cudaFuncSetAttribute(attn_kernel, cudaFuncAttributeMaxDynamicSharedMemorySize, (int)smem);
    attn_kernel<<<dim3(CHn, NHn, Bn), 256, smem>>>(out);
}

// round 3
// speedup vs baseline: 1.7078x; 1.7078x over previous
#include <cuda_runtime.h>
#include <cuda_bf16.h>
#include <cstdint>
#include <math.h>

#define Bn 16
#define Sn 768
#define Hn 768
#define Tn 128
#define NQn 640
#define DHn 64
#define NHn 12
#define CHn 10
#define Mn (Bn * Sn)   // 12288

// ---------------- device scratch (no cudaMalloc allowed) -------------------
__device__ float g_Q[(size_t)Mn * Hn];
__device__ float g_K[(size_t)Mn * Hn];
__device__ float g_V[(size_t)Mn * Hn];
__device__ float g_Vsum[Bn * Hn];
__device__ __nv_bfloat16 g_hs_hi[(size_t)Mn * Hn];
__device__ __nv_bfloat16 g_hs_lo[(size_t)Mn * Hn];
__device__ __nv_bfloat16 g_W_hi[3 * Hn * Hn];
__device__ __nv_bfloat16 g_W_lo[3 * Hn * Hn];

// ---------------------------------------------------------------------------
// fp32 -> (bf16 hi, bf16 lo) split conversions
// ---------------------------------------------------------------------------
__global__ void cvt_hs(const float* __restrict__ hs)
{
    const int n = Mn * Hn;
    for (int i = blockIdx.x * blockDim.x + threadIdx.x; i < n;
         i += gridDim.x * blockDim.x) {
        float x = hs[i];
        __nv_bfloat16 hi = __float2bfloat16(x);
        g_hs_hi[i] = hi;
        g_hs_lo[i] = __float2bfloat16(x - __bfloat162float(hi));
    }
}

__global__ void cvt_w(const float* __restrict__ Wq, const float* __restrict__ Wk,
                      const float* __restrict__ Wv)
{
    const int n = Hn * Hn;
    for (int i = blockIdx.x * blockDim.x + threadIdx.x; i < 3 * n;
         i += gridDim.x * blockDim.x) {
        int z = i / n, j = i - z * n;
        const float* W = (z == 0) ? Wq : (z == 1) ? Wk : Wv;
        float x = W[j];
        __nv_bfloat16 hi = __float2bfloat16(x);
        g_W_hi[i] = hi;
        g_W_lo[i] = __float2bfloat16(x - __bfloat162float(hi));
    }
}

// ---------------------------------------------------------------------------
// Compensated bf16 tensor-core GEMM:  C = A @ W^T + bias
//   C ~= Ahi@Whi^T + Ahi@Wlo^T + Alo@Whi^T   (fp32 accumulate)
// 128x128 tile, BK=32, 256 threads (8 warps, 2x4), mma.sync m16n8k16.
// grid = (Hn/128, Mn/128, 3); z selects Q/K/V.
// ---------------------------------------------------------------------------
__device__ __forceinline__ void mma_bf16(float c[4], uint32_t a0, uint32_t a1,
                                         uint32_t a2, uint32_t a3,
                                         uint32_t b0, uint32_t b1)
{
    asm volatile(
        "mma.sync.aligned.m16n8k16.row.col.f32.bf16.bf16.f32 "
        "{%0,%1,%2,%3}, {%4,%5,%6,%7}, {%8,%9}, {%0,%1,%2,%3};\n"
        : "+f"(c[0]), "+f"(c[1]), "+f"(c[2]), "+f"(c[3])
        : "r"(a0), "r"(a1), "r"(a2), "r"(a3), "r"(b0), "r"(b1));
}

#define CPASYNC16(saddr, gptr) \
    asm volatile("cp.async.cg.shared.global [%0], [%1], 16;\n" :: "r"(saddr), "l"(gptr))
#define CP_COMMIT() asm volatile("cp.async.commit_group;\n")
#define CP_WAIT(N)  asm volatile("cp.async.wait_group %0;\n" :: "n"(N))

#define TILE_ELEMS (128 * 40)   // padded: 32 bf16 data + 8 pad per row

__global__ __launch_bounds__(256, 1) void gemm_qkv(
    const float* __restrict__ bq, const float* __restrict__ bk,
    const float* __restrict__ bv)
{
    extern __shared__ __nv_bfloat16 smem[];
    // smem: [buf(2)][array(4: Ahi,Alo,Whi,Wlo)][TILE_ELEMS]

    const int tid = threadIdx.x;
    const int rowBase = blockIdx.y * 128;
    const int colBase = blockIdx.x * 128;
    const int z = blockIdx.z;

    const __nv_bfloat16* Ahi = g_hs_hi + (size_t)rowBase * Hn;
    const __nv_bfloat16* Alo = g_hs_lo + (size_t)rowBase * Hn;
    const __nv_bfloat16* Whi = g_W_hi + (size_t)z * Hn * Hn + (size_t)colBase * Hn;
    const __nv_bfloat16* Wlo = g_W_lo + (size_t)z * Hn * Hn + (size_t)colBase * Hn;
    float* C = (z == 0) ? g_Q : (z == 1) ? g_K : g_V;
    const float* bias = (z == 0) ? bq : (z == 1) ? bk : bv;

    // loader mapping: 512 16B-chunks per tile, 2 per thread
    const int lrow = tid >> 2;          // 0..63 (and +64)
    const int lkc  = (tid & 3) * 8;     // bf16 col offset: 0,8,16,24

    const int warp  = tid >> 5;
    const int lane  = tid & 31;
    const int warpM = warp >> 2;        // 0..1 -> 64 rows each
    const int warpN = warp & 3;         // 0..3 -> 32 cols each
    const int g  = lane >> 2;           // 0..7
    const int tq = lane & 3;            // 0..3
    const int mrow = warpM * 64;
    const int nrow = warpN * 32;

    float acc[4][4][4];
#pragma unroll
    for (int mi = 0; mi < 4; mi++)
#pragma unroll
        for (int ni = 0; ni < 4; ni++)
#pragma unroll
            for (int r = 0; r < 4; r++) acc[mi][ni][r] = 0.f;

    auto load_tiles = [&](int buf, int k0) {
        __nv_bfloat16* s = smem + buf * 4 * TILE_ELEMS;
#pragma unroll
        for (int r2 = 0; r2 < 2; r2++) {
            int r = lrow + r2 * 64;
            int so = r * 40 + lkc;
            size_t go = (size_t)r * Hn + k0 + lkc;
            CPASYNC16((uint32_t)__cvta_generic_to_shared(s + 0 * TILE_ELEMS + so), Ahi + go);
            CPASYNC16((uint32_t)__cvta_generic_to_shared(s + 1 * TILE_ELEMS + so), Alo + go);
            CPASYNC16((uint32_t)__cvta_generic_to_shared(s + 2 * TILE_ELEMS + so), Whi + go);
            CPASYNC16((uint32_t)__cvta_generic_to_shared(s + 3 * TILE_ELEMS + so), Wlo + go);
        }
    };

    auto compute = [&](int buf) {
        const uint32_t* sAhi = (const uint32_t*)(smem + (buf * 4 + 0) * TILE_ELEMS);
        const uint32_t* sAlo = (const uint32_t*)(smem + (buf * 4 + 1) * TILE_ELEMS);
        const uint32_t* sWhi = (const uint32_t*)(smem + (buf * 4 + 2) * TILE_ELEMS);
        const uint32_t* sWlo = (const uint32_t*)(smem + (buf * 4 + 3) * TILE_ELEMS);
#pragma unroll
        for (int ks = 0; ks < 2; ks++) {
            const int kw = ks * 8 + tq;     // word offset within padded row (20 words)
            uint32_t ahi[4][4], bhi[4][2];
#pragma unroll
            for (int mi = 0; mi < 4; mi++) {
                int r = mrow + mi * 16 + g;
                ahi[mi][0] = sAhi[r * 20 + kw];
                ahi[mi][1] = sAhi[(r + 8) * 20 + kw];
                ahi[mi][2] = sAhi[r * 20 + kw + 4];
                ahi[mi][3] = sAhi[(r + 8) * 20 + kw + 4];
            }
#pragma unroll
            for (int ni = 0; ni < 4; ni++) {
                int n = nrow + ni * 8 + g;
                bhi[ni][0] = sWhi[n * 20 + kw];
                bhi[ni][1] = sWhi[n * 20 + kw + 4];
            }
            // product 1: Ahi x Whi
#pragma unroll
            for (int mi = 0; mi < 4; mi++)
#pragma unroll
                for (int ni = 0; ni < 4; ni++)
                    mma_bf16(acc[mi][ni], ahi[mi][0], ahi[mi][1], ahi[mi][2],
                             ahi[mi][3], bhi[ni][0], bhi[ni][1]);
            // product 2: Ahi x Wlo
            {
                uint32_t blo[4][2];
#pragma unroll
                for (int ni = 0; ni < 4; ni++) {
                    int n = nrow + ni * 8 + g;
                    blo[ni][0] = sWlo[n * 20 + kw];
                    blo[ni][1] = sWlo[n * 20 + kw + 4];
                }
#pragma unroll
                for (int mi = 0; mi < 4; mi++)
#pragma unroll
                    for (int ni = 0; ni < 4; ni++)
                        mma_bf16(acc[mi][ni], ahi[mi][0], ahi[mi][1], ahi[mi][2],
                                 ahi[mi][3], blo[ni][0], blo[ni][1]);
            }
            // product 3: Alo x Whi
            {
                uint32_t alo[4][4];
#pragma unroll
                for (int mi = 0; mi < 4; mi++) {
                    int r = mrow + mi * 16 + g;
                    alo[mi][0] = sAlo[r * 20 + kw];
                    alo[mi][1] = sAlo[(r + 8) * 20 + kw];
                    alo[mi][2] = sAlo[r * 20 + kw + 4];
                    alo[mi][3] = sAlo[(r + 8) * 20 + kw + 4];
                }
#pragma unroll
                for (int mi = 0; mi < 4; mi++)
#pragma unroll
                    for (int ni = 0; ni < 4; ni++)
                        mma_bf16(acc[mi][ni], alo[mi][0], alo[mi][1], alo[mi][2],
                                 alo[mi][3], bhi[ni][0], bhi[ni][1]);
            }
        }
    };

    load_tiles(0, 0);
    CP_COMMIT();

    const int NKT = Hn / 32;   // 24
    for (int kt = 0; kt < NKT; kt++) {
        if (kt + 1 < NKT) {
            load_tiles((kt + 1) & 1, (kt + 1) * 32);
            CP_COMMIT();
            CP_WAIT(1);
        } else {
            CP_WAIT(0);
        }
        __syncthreads();
        compute(kt & 1);
        __syncthreads();
    }

    // epilogue: add bias, store fp32
#pragma unroll
    for (int mi = 0; mi < 4; mi++) {
#pragma unroll
        for (int ni = 0; ni < 4; ni++) {
            int row0 = rowBase + mrow + mi * 16 + g;
            int col0 = colBase + nrow + ni * 8 + 2 * tq;
            float b0 = bias[col0], b1 = bias[col0 + 1];
            float2 v0 = make_float2(acc[mi][ni][0] + b0, acc[mi][ni][1] + b1);
            float2 v1 = make_float2(acc[mi][ni][2] + b0, acc[mi][ni][3] + b1);
            *(float2*)(C + (size_t)row0 * Hn + col0) = v0;
            *(float2*)(C + (size_t)(row0 + 8) * Hn + col0) = v1;
        }
    }
}

// ---------------------------------------------------------------------------
// Vsum: per-(b, col) sum of V over first 640 rows (zero + chunk partials)
// ---------------------------------------------------------------------------
__global__ void vsum_zero()
{
    g_Vsum[blockIdx.x * Hn + threadIdx.x] = 0.f;
}

__global__ void vsum_part()
{
    int b = blockIdx.x, c = blockIdx.y;
    int col = threadIdx.x;
    const float* base = g_V + ((size_t)b * Sn + c * 64) * Hn + col;
    float acc = 0.f;
#pragma unroll 8
    for (int s = 0; s < 64; s++) acc += base[(size_t)s * Hn];
    atomicAdd(&g_Vsum[b * Hn + col], acc);
}

// ---------------------------------------------------------------------------
// Output rows >= 640 are the raw V projection rows.
// ---------------------------------------------------------------------------
__global__ void tail_copy(float* __restrict__ out)
{
    int b = blockIdx.x / Tn;
    int t = blockIdx.x % Tn;
    size_t r = (size_t)b * Sn + NQn + t;
    out[r * Hn + threadIdx.x] = g_V[r * Hn + threadIdx.x];
}

// ---------------------------------------------------------------------------
// Fused attention: one CTA per (chunk, head, batch).
// 64 queries x 192 keys (64 chunk + 128 tail); masked columns folded in via
// exp(-m) * (Vsum640 - Vchunk) correction.
// ---------------------------------------------------------------------------
__global__ __launch_bounds__(256) void attn_kernel(float* __restrict__ out)
{
    extern __shared__ float sm[];
    float* sq  = sm;                    // 64 * 65
    float* sk  = sq + 64 * 65;          // 192 * 65
    float* sv  = sk + 192 * 65;         // 192 * 65
    float* sp  = sv + 192 * 65;         // 64 * 192
    float* sem = sp + 64 * 192;         // 64
    float* sz  = sem + 64;              // 64
    float* sms = sz + 64;               // 64

    const int tid = threadIdx.x;
    const int chunk = blockIdx.x;
    const int h = blockIdx.y;
    const int b = blockIdx.z;

    const size_t rowQ0 = ((size_t)b * Sn + chunk * 64) * Hn + h * DHn;
    for (int idx = tid; idx < 64 * 64; idx += 256) {
        int i = idx >> 6, d = idx & 63;
        sq[i * 65 + d] = g_Q[rowQ0 + (size_t)i * Hn + d];
    }
    for (int idx = tid; idx < 192 * 64; idx += 256) {
        int j = idx >> 6, d = idx & 63;
        int s = (j < 64) ? (chunk * 64 + j) : (576 + j);
        size_t off = ((size_t)b * Sn + s) * Hn + h * DHn + d;
        sk[j * 65 + d] = g_K[off];
        sv[j * 65 + d] = g_V[off];
    }
    __syncthreads();

    const int tx = tid & 15;
    const int ty = tid >> 4;

    {
        float acc[4][12];
#pragma unroll
        for (int ii = 0; ii < 4; ii++)
#pragma unroll
            for (int jj = 0; jj < 12; jj++) acc[ii][jj] = 0.f;
        const int i0 = ty * 4, j0 = tx * 12;
        for (int d = 0; d < 64; d++) {
            float a[4], kb[12];
#pragma unroll
            for (int ii = 0; ii < 4; ii++) a[ii] = sq[(i0 + ii) * 65 + d];
#pragma unroll
            for (int jj = 0; jj < 12; jj++) kb[jj] = sk[(j0 + jj) * 65 + d];
#pragma unroll
            for (int ii = 0; ii < 4; ii++)
#pragma unroll
                for (int jj = 0; jj < 12; jj++)
                    acc[ii][jj] = fmaf(a[ii], kb[jj], acc[ii][jj]);
        }
#pragma unroll
        for (int ii = 0; ii < 4; ii++)
#pragma unroll
            for (int jj = 0; jj < 12; jj++)
                sp[(i0 + ii) * 192 + j0 + jj] = acc[ii][jj] * 0.125f;
    }
    __syncthreads();

    if (tid < 64) {
        const int i = tid;
        float m = 0.f;
        for (int j = 0; j < 192; j++) m = fmaxf(m, sp[i * 192 + j]);
        float Z = 0.f;
        for (int j = 0; j < 192; j++) {
            float e = __expf(sp[i * 192 + j] - m);
            sp[i * 192 + j] = e;
            Z += e;
        }
        float em = __expf(-m);
        Z += 576.f * em;
        sem[i] = em;
        sz[i]  = 1.f / Z;
    } else if (tid < 128) {
        const int d = tid - 64;
        float acc = 0.f;
        for (int j = 0; j < 64; j++) acc += sv[j * 65 + d];
        sms[d] = g_Vsum[b * Hn + h * DHn + d] - acc;
    }
    __syncthreads();

    {
        float acc[4][4];
#pragma unroll
        for (int ii = 0; ii < 4; ii++)
#pragma unroll
            for (int dd = 0; dd < 4; dd++) acc[ii][dd] = 0.f;
        const int i0 = ty * 4, d0 = tx * 4;
        for (int j = 0; j < 192; j++) {
            float pv[4], vj[4];
#pragma unroll
            for (int ii = 0; ii < 4; ii++) pv[ii] = sp[(i0 + ii) * 192 + j];
#pragma unroll
            for (int dd = 0; dd < 4; dd++) vj[dd] = sv[j * 65 + d0 + dd];
#pragma unroll
            for (int ii = 0; ii < 4; ii++)
#pragma unroll
                for (int dd = 0; dd < 4; dd++)
                    acc[ii][dd] = fmaf(pv[ii], vj[dd], acc[ii][dd]);
        }
#pragma unroll
        for (int ii = 0; ii < 4; ii++) {
            float* orow = out + ((size_t)b * Sn + chunk * 64 + i0 + ii) * Hn + h * DHn + d0;
            float inv = sz[i0 + ii];
            float em  = sem[i0 + ii];
#pragma unroll
            for (int dd = 0; dd < 4; dd++)
                orow[dd] = (acc[ii][dd] + em * sms[d0 + dd]) * inv;
        }
    }
}

// ---------------------------------------------------------------------------
extern "C" void kernel_launch(void* const* d_in, const int* in_sizes, int n_in,
                              void* d_out, int out_size)
{
    const float* hs = (const float*)d_in[0];
    const float* Wq = (const float*)d_in[1];
    const float* bq = (const float*)d_in[2];
    const float* Wk = (const float*)d_in[3];
    const float* bk = (const float*)d_in[4];
    const float* Wv = (const float*)d_in[5];
    const float* bv = (const float*)d_in[6];
    float* out = (float*)d_out;

    cvt_hs<<<4096, 256>>>(hs);
    cvt_w<<<2048, 256>>>(Wq, Wk, Wv);

    const int gemm_smem = 2 * 4 * TILE_ELEMS * 2;   // 81920 bytes
    cudaFuncSetAttribute(gemm_qkv, cudaFuncAttributeMaxDynamicSharedMemorySize, gemm_smem);
    gemm_qkv<<<dim3(Hn / 128, Mn / 128, 3), 256, gemm_smem>>>(bq, bk, bv);

    vsum_zero<<<Bn, Hn>>>();
    vsum_part<<<dim3(Bn, CHn), Hn>>>();
    tail_copy<<<Bn * Tn, Hn>>>(out);

    const size_t smem = (size_t)(64 * 65 + 2 * 192 * 65 + 64 * 192 + 3 * 64) * sizeof(float);
    cudaFuncSetAttribute(attn_kernel, cudaFuncAttributeMaxDynamicSharedMemorySize, (int)smem);
    attn_kernel<<<dim3(CHn, NHn, Bn), 256, smem>>>(out);
}

// round 4
// speedup vs baseline: 1.7483x; 1.0237x over previous
#include <cuda_runtime.h>
#include <cuda_bf16.h>
#include <cstdint>
#include <math.h>

#define Bn 16
#define Sn 768
#define Hn 768
#define Tn 128
#define NQn 640
#define DHn 64
#define NHn 12
#define CHn 10
#define Mn (Bn * Sn)   // 12288

// ---------------- device scratch (no cudaMalloc allowed) -------------------
__device__ float g_Q[(size_t)Mn * Hn];
__device__ float g_K[(size_t)Mn * Hn];
__device__ float g_V[(size_t)Mn * Hn];
__device__ float g_Vsum[Bn * Hn];
__device__ __nv_bfloat16 g_hs_hi[(size_t)Mn * Hn];
__device__ __nv_bfloat16 g_hs_lo[(size_t)Mn * Hn];
__device__ __nv_bfloat16 g_W_hi[3 * Hn * Hn];
__device__ __nv_bfloat16 g_W_lo[3 * Hn * Hn];

// ---------------------------------------------------------------------------
// fp32 -> (bf16 hi, bf16 lo) split conversions (vectorized)
// ---------------------------------------------------------------------------
__global__ void cvt_hs(const float* __restrict__ hs)
{
    const int n4 = (Mn * Hn) / 4;
    __nv_bfloat162* hi2 = (__nv_bfloat162*)g_hs_hi;
    __nv_bfloat162* lo2 = (__nv_bfloat162*)g_hs_lo;
    for (int i = blockIdx.x * blockDim.x + threadIdx.x; i < n4;
         i += gridDim.x * blockDim.x) {
        float4 x = ((const float4*)hs)[i];
        __nv_bfloat16 h0 = __float2bfloat16(x.x), h1 = __float2bfloat16(x.y);
        __nv_bfloat16 h2 = __float2bfloat16(x.z), h3 = __float2bfloat16(x.w);
        hi2[2 * i + 0] = __nv_bfloat162(h0, h1);
        hi2[2 * i + 1] = __nv_bfloat162(h2, h3);
        lo2[2 * i + 0] = __nv_bfloat162(
            __float2bfloat16(x.x - __bfloat162float(h0)),
            __float2bfloat16(x.y - __bfloat162float(h1)));
        lo2[2 * i + 1] = __nv_bfloat162(
            __float2bfloat16(x.z - __bfloat162float(h2)),
            __float2bfloat16(x.w - __bfloat162float(h3)));
    }
}

__global__ void cvt_w(const float* __restrict__ Wq, const float* __restrict__ Wk,
                      const float* __restrict__ Wv)
{
    const int n = Hn * Hn;
    for (int i = blockIdx.x * blockDim.x + threadIdx.x; i < 3 * n;
         i += gridDim.x * blockDim.x) {
        int z = i / n, j = i - z * n;
        const float* W = (z == 0) ? Wq : (z == 1) ? Wk : Wv;
        float x = W[j];
        __nv_bfloat16 hi = __float2bfloat16(x);
        g_W_hi[i] = hi;
        g_W_lo[i] = __float2bfloat16(x - __bfloat162float(hi));
    }
}

// ---------------------------------------------------------------------------
// Compensated bf16 tensor-core GEMM:  C = A @ W^T + bias
// 128x128 tile, BK=32, 256 threads (8 warps 2x4), ldmatrix + 3-stage cp.async.
// ---------------------------------------------------------------------------
__device__ __forceinline__ void mma_bf16(float c[4], uint32_t a0, uint32_t a1,
                                         uint32_t a2, uint32_t a3,
                                         uint32_t b0, uint32_t b1)
{
    asm volatile(
        "mma.sync.aligned.m16n8k16.row.col.f32.bf16.bf16.f32 "
        "{%0,%1,%2,%3}, {%4,%5,%6,%7}, {%8,%9}, {%0,%1,%2,%3};\n"
        : "+f"(c[0]), "+f"(c[1]), "+f"(c[2]), "+f"(c[3])
        : "r"(a0), "r"(a1), "r"(a2), "r"(a3), "r"(b0), "r"(b1));
}

__device__ __forceinline__ void ldsm_x4(uint32_t& r0, uint32_t& r1, uint32_t& r2,
                                        uint32_t& r3, uint32_t saddr)
{
    asm volatile("ldmatrix.sync.aligned.m8n8.x4.shared.b16 {%0,%1,%2,%3}, [%4];\n"
                 : "=r"(r0), "=r"(r1), "=r"(r2), "=r"(r3) : "r"(saddr));
}

#define CPASYNC16(saddr, gptr) \
    asm volatile("cp.async.cg.shared.global [%0], [%1], 16;\n" :: "r"(saddr), "l"(gptr))
#define CP_COMMIT() asm volatile("cp.async.commit_group;\n")
#define CP_WAIT(N)  asm volatile("cp.async.wait_group %0;\n" :: "n"(N))

#define TILE_ELEMS (128 * 40)           // bf16 elems per array (32 data + 8 pad/row)
#define STAGE_BYTES (4 * TILE_ELEMS * 2)  // 40960
#define NSTAGE 3

__global__ __launch_bounds__(256, 1) void gemm_qkv(
    const float* __restrict__ bq, const float* __restrict__ bk,
    const float* __restrict__ bv)
{
    extern __shared__ __nv_bfloat16 smem[];

    const int tid = threadIdx.x;
    const int rowBase = blockIdx.y * 128;
    const int colBase = blockIdx.x * 128;
    const int z = blockIdx.z;

    const __nv_bfloat16* Ahi = g_hs_hi + (size_t)rowBase * Hn;
    const __nv_bfloat16* Alo = g_hs_lo + (size_t)rowBase * Hn;
    const __nv_bfloat16* Whi = g_W_hi + (size_t)z * Hn * Hn + (size_t)colBase * Hn;
    const __nv_bfloat16* Wlo = g_W_lo + (size_t)z * Hn * Hn + (size_t)colBase * Hn;
    float* C = (z == 0) ? g_Q : (z == 1) ? g_K : g_V;
    const float* bias = (z == 0) ? bq : (z == 1) ? bk : bv;

    const uint32_t sbase = (uint32_t)__cvta_generic_to_shared(smem);

    // loader mapping: per array 128 rows x 4 chunks(16B); 2 rows per thread
    const int lrow = tid >> 2;
    const int lkc  = (tid & 3) * 8;

    const int warp  = tid >> 5;
    const int lane  = tid & 31;
    const int warpM = warp >> 2;
    const int warpN = warp & 3;
    const int g  = lane >> 2;
    const int tq = lane & 3;
    const int mrow = warpM * 64;
    const int nrow = warpN * 32;
    // ldmatrix per-lane offset: row-sel + k-half-sel
    const int rsel = lane & 15;
    const int ksel = lane >> 4;
    const uint32_t laneoff = (uint32_t)(rsel * 80 + ksel * 16);

    float acc[4][4][4];
#pragma unroll
    for (int mi = 0; mi < 4; mi++)
#pragma unroll
        for (int ni = 0; ni < 4; ni++)
#pragma unroll
            for (int r = 0; r < 4; r++) acc[mi][ni][r] = 0.f;

    auto load_tiles = [&](int stage, int k0) {
        uint32_t s0 = sbase + stage * STAGE_BYTES;
#pragma unroll
        for (int r2 = 0; r2 < 2; r2++) {
            int r = lrow + r2 * 64;
            uint32_t so = (uint32_t)(r * 80 + lkc * 2);
            size_t go = (size_t)r * Hn + k0 + lkc;
            CPASYNC16(s0 + 0 * (TILE_ELEMS * 2) + so, Ahi + go);
            CPASYNC16(s0 + 1 * (TILE_ELEMS * 2) + so, Alo + go);
            CPASYNC16(s0 + 2 * (TILE_ELEMS * 2) + so, Whi + go);
            CPASYNC16(s0 + 3 * (TILE_ELEMS * 2) + so, Wlo + go);
        }
    };

    auto compute = [&](int stage) {
        uint32_t s0 = sbase + stage * STAGE_BYTES;
        const uint32_t sAhi = s0 + 0 * (TILE_ELEMS * 2) + laneoff;
        const uint32_t sAlo = s0 + 1 * (TILE_ELEMS * 2) + laneoff;
        const uint32_t sWhi = s0 + 2 * (TILE_ELEMS * 2) + laneoff;
        const uint32_t sWlo = s0 + 3 * (TILE_ELEMS * 2) + laneoff;
#pragma unroll
        for (int ks = 0; ks < 2; ks++) {
            const uint32_t ko = (uint32_t)(ks * 32);
            uint32_t ahi[4][4], bhi[4][2];
#pragma unroll
            for (int nj = 0; nj < 2; nj++) {
                uint32_t r0, r1, r2, r3;
                ldsm_x4(r0, r1, r2, r3, sWhi + (uint32_t)((nrow + nj * 16) * 80) + ko);
                bhi[nj * 2 + 0][0] = r0; bhi[nj * 2 + 1][0] = r1;
                bhi[nj * 2 + 0][1] = r2; bhi[nj * 2 + 1][1] = r3;
            }
#pragma unroll
            for (int mi = 0; mi < 4; mi++)
                ldsm_x4(ahi[mi][0], ahi[mi][1], ahi[mi][2], ahi[mi][3],
                        sAhi + (uint32_t)((mrow + mi * 16) * 80) + ko);
            // product 1: Ahi x Whi
#pragma unroll
            for (int mi = 0; mi < 4; mi++)
#pragma unroll
                for (int ni = 0; ni < 4; ni++)
                    mma_bf16(acc[mi][ni], ahi[mi][0], ahi[mi][1], ahi[mi][2],
                             ahi[mi][3], bhi[ni][0], bhi[ni][1]);
            // product 2: Ahi x Wlo
            {
                uint32_t blo[4][2];
#pragma unroll
                for (int nj = 0; nj < 2; nj++) {
                    uint32_t r0, r1, r2, r3;
                    ldsm_x4(r0, r1, r2, r3, sWlo + (uint32_t)((nrow + nj * 16) * 80) + ko);
                    blo[nj * 2 + 0][0] = r0; blo[nj * 2 + 1][0] = r1;
                    blo[nj * 2 + 0][1] = r2; blo[nj * 2 + 1][1] = r3;
                }
#pragma unroll
                for (int mi = 0; mi < 4; mi++)
#pragma unroll
                    for (int ni = 0; ni < 4; ni++)
                        mma_bf16(acc[mi][ni], ahi[mi][0], ahi[mi][1], ahi[mi][2],
                                 ahi[mi][3], blo[ni][0], blo[ni][1]);
            }
            // product 3: Alo x Whi
            {
                uint32_t alo[4][4];
#pragma unroll
                for (int mi = 0; mi < 4; mi++)
                    ldsm_x4(alo[mi][0], alo[mi][1], alo[mi][2], alo[mi][3],
                            sAlo + (uint32_t)((mrow + mi * 16) * 80) + ko);
#pragma unroll
                for (int mi = 0; mi < 4; mi++)
#pragma unroll
                    for (int ni = 0; ni < 4; ni++)
                        mma_bf16(acc[mi][ni], alo[mi][0], alo[mi][1], alo[mi][2],
                                 alo[mi][3], bhi[ni][0], bhi[ni][1]);
            }
        }
    };

    const int NKT = Hn / 32;   // 24
    load_tiles(0, 0);
    CP_COMMIT();
    load_tiles(1, 32);
    CP_COMMIT();

    for (int kt = 0; kt < NKT; kt++) {
        if (kt < NKT - 1) { CP_WAIT(1); } else { CP_WAIT(0); }
        __syncthreads();
        if (kt + 2 < NKT) {
            load_tiles((kt + 2) % NSTAGE, (kt + 2) * 32);
            CP_COMMIT();
        }
        compute(kt % NSTAGE);
    }

    // epilogue: add bias, store fp32
#pragma unroll
    for (int mi = 0; mi < 4; mi++) {
#pragma unroll
        for (int ni = 0; ni < 4; ni++) {
            int row0 = rowBase + mrow + mi * 16 + g;
            int col0 = colBase + nrow + ni * 8 + 2 * tq;
            float b0 = bias[col0], b1 = bias[col0 + 1];
            float2 v0 = make_float2(acc[mi][ni][0] + b0, acc[mi][ni][1] + b1);
            float2 v1 = make_float2(acc[mi][ni][2] + b0, acc[mi][ni][3] + b1);
            *(float2*)(C + (size_t)row0 * Hn + col0) = v0;
            *(float2*)(C + (size_t)(row0 + 8) * Hn + col0) = v1;
        }
    }
}

// ---------------------------------------------------------------------------
__global__ void vsum_zero()
{
    g_Vsum[blockIdx.x * Hn + threadIdx.x] = 0.f;
}

__global__ void vsum_part()
{
    int b = blockIdx.x, c = blockIdx.y;
    int col = threadIdx.x;
    const float* base = g_V + ((size_t)b * Sn + c * 64) * Hn + col;
    float acc = 0.f;
#pragma unroll 8
    for (int s = 0; s < 64; s++) acc += base[(size_t)s * Hn];
    atomicAdd(&g_Vsum[b * Hn + col], acc);
}

__global__ void tail_copy(float* __restrict__ out)
{
    int b = blockIdx.x / Tn;
    int t = blockIdx.x % Tn;
    size_t r = (size_t)b * Sn + NQn + t;
    out[r * Hn + threadIdx.x] = g_V[r * Hn + threadIdx.x];
}

// ---------------------------------------------------------------------------
// Fused attention (512 threads): one CTA per (chunk, head, batch).
// 64 q x 192 keys; masked cols folded via exp(-m)*(Vsum640 - Vchunk).
// Layout: sk stride 65 (conflict-free interleaved j), sv stride 68 (float4),
// sp stride 193 (skewed).
// ---------------------------------------------------------------------------
#define SKS 65
#define SVS 68
#define SPS 193

__global__ __launch_bounds__(512) void attn_kernel(float* __restrict__ out)
{
    extern __shared__ float sm[];
    float* sq  = sm;                    // 64 * 65
    float* sk  = sq + 64 * SKS;         // 192 * 65
    float* sv  = sk + 192 * SKS;        // 192 * 68
    float* sp  = sv + 192 * SVS;        // 64 * 193
    float* sem = sp + 64 * SPS;         // 64
    float* sz  = sem + 64;              // 64
    float* sms = sz + 64;               // 64

    const int tid = threadIdx.x;
    const int chunk = blockIdx.x;
    const int h = blockIdx.y;
    const int b = blockIdx.z;

    const size_t rowQ0 = ((size_t)b * Sn + chunk * 64) * Hn + h * DHn;
    for (int idx = tid; idx < 64 * 64; idx += 512) {
        int i = idx >> 6, d = idx & 63;
        sq[i * SKS + d] = g_Q[rowQ0 + (size_t)i * Hn + d];
    }
    for (int idx = tid; idx < 192 * 64; idx += 512) {
        int j = idx >> 6, d = idx & 63;
        int s = (j < 64) ? (chunk * 64 + j) : (576 + j);
        size_t off = ((size_t)b * Sn + s) * Hn + h * DHn + d;
        sk[j * SKS + d] = g_K[off];
        sv[j * SVS + d] = g_V[off];
    }
    __syncthreads();

    const int tx = tid & 15;
    const int ty = tid >> 4;      // 0..31
    const int i0 = ty * 2;

    // scores: 2 rows x 12 interleaved cols per thread (j = tx + 16*jj)
    {
        float acc[2][12];
#pragma unroll
        for (int ii = 0; ii < 2; ii++)
#pragma unroll
            for (int jj = 0; jj < 12; jj++) acc[ii][jj] = 0.f;
        for (int d = 0; d < 64; d++) {
            float a0 = sq[i0 * SKS + d];
            float a1 = sq[(i0 + 1) * SKS + d];
            float kb[12];
#pragma unroll
            for (int jj = 0; jj < 12; jj++) kb[jj] = sk[(tx + 16 * jj) * SKS + d];
#pragma unroll
            for (int jj = 0; jj < 12; jj++) {
                acc[0][jj] = fmaf(a0, kb[jj], acc[0][jj]);
                acc[1][jj] = fmaf(a1, kb[jj], acc[1][jj]);
            }
        }
#pragma unroll
        for (int ii = 0; ii < 2; ii++)
#pragma unroll
            for (int jj = 0; jj < 12; jj++)
                sp[(i0 + ii) * SPS + tx + 16 * jj] = acc[ii][jj] * 0.125f;
    }
    __syncthreads();

    // masked-v sum: d = tid/8, 8 threads sum 8 chunk-rows each
    {
        const int d = tid >> 3, part = tid & 7;
        float s = 0.f;
#pragma unroll
        for (int j = part * 8; j < part * 8 + 8; j++) s += sv[j * SVS + d];
        s += __shfl_xor_sync(0xFFFFFFFFu, s, 1);
        s += __shfl_xor_sync(0xFFFFFFFFu, s, 2);
        s += __shfl_xor_sync(0xFFFFFFFFu, s, 4);
        if (part == 0) sms[d] = g_Vsum[b * Hn + h * DHn + d] - s;
    }

    // softmax: row = tid/8, 8 threads x 24 cols; masked cols add 576*exp(-m)
    {
        const int i = tid >> 3, part = tid & 7;
        const int j0 = part * 24;
        float m = 0.f;   // masked scores are exactly 0
#pragma unroll
        for (int j = j0; j < j0 + 24; j++) m = fmaxf(m, sp[i * SPS + j]);
        m = fmaxf(m, __shfl_xor_sync(0xFFFFFFFFu, m, 1));
        m = fmaxf(m, __shfl_xor_sync(0xFFFFFFFFu, m, 2));
        m = fmaxf(m, __shfl_xor_sync(0xFFFFFFFFu, m, 4));
        float Z = 0.f;
#pragma unroll
        for (int j = j0; j < j0 + 24; j++) {
            float e = __expf(sp[i * SPS + j] - m);
            sp[i * SPS + j] = e;
            Z += e;
        }
        Z += __shfl_xor_sync(0xFFFFFFFFu, Z, 1);
        Z += __shfl_xor_sync(0xFFFFFFFFu, Z, 2);
        Z += __shfl_xor_sync(0xFFFFFFFFu, Z, 4);
        if (part == 0) {
            float em = __expf(-m);
            sem[i] = em;
            sz[i] = 1.f / (Z + 576.f * em);
        }
    }
    __syncthreads();

    // ctx: 2 rows x 4 cols per thread over 192 keys
    {
        float acc[2][4];
#pragma unroll
        for (int ii = 0; ii < 2; ii++)
#pragma unroll
            for (int dd = 0; dd < 4; dd++) acc[ii][dd] = 0.f;
        const int d0 = tx * 4;
        for (int j = 0; j < 192; j++) {
            float p0 = sp[i0 * SPS + j];
            float p1 = sp[(i0 + 1) * SPS + j];
            float4 vj = *(const float4*)&sv[j * SVS + d0];
            acc[0][0] = fmaf(p0, vj.x, acc[0][0]);
            acc[0][1] = fmaf(p0, vj.y, acc[0][1]);
            acc[0][2] = fmaf(p0, vj.z, acc[0][2]);
            acc[0][3] = fmaf(p0, vj.w, acc[0][3]);
            acc[1][0] = fmaf(p1, vj.x, acc[1][0]);
            acc[1][1] = fmaf(p1, vj.y, acc[1][1]);
            acc[1][2] = fmaf(p1, vj.z, acc[1][2]);
            acc[1][3] = fmaf(p1, vj.w, acc[1][3]);
        }
#pragma unroll
        for (int ii = 0; ii < 2; ii++) {
            float inv = sz[i0 + ii];
            float em  = sem[i0 + ii];
            float4 o;
            o.x = (acc[ii][0] + em * sms[d0 + 0]) * inv;
            o.y = (acc[ii][1] + em * sms[d0 + 1]) * inv;
            o.z = (acc[ii][2] + em * sms[d0 + 2]) * inv;
            o.w = (acc[ii][3] + em * sms[d0 + 3]) * inv;
            *(float4*)(out + ((size_t)b * Sn + chunk * 64 + i0 + ii) * Hn + h * DHn + d0) = o;
        }
    }
}

// ---------------------------------------------------------------------------
extern "C" void kernel_launch(void* const* d_in, const int* in_sizes, int n_in,
                              void* d_out, int out_size)
{
    const float* hs = (const float*)d_in[0];
    const float* Wq = (const float*)d_in[1];
    const float* bq = (const float*)d_in[2];
    const float* Wk = (const float*)d_in[3];
    const float* bk = (const float*)d_in[4];
    const float* Wv = (const float*)d_in[5];
    const float* bv = (const float*)d_in[6];
    float* out = (float*)d_out;

    cvt_hs<<<2048, 256>>>(hs);
    cvt_w<<<2048, 256>>>(Wq, Wk, Wv);
    vsum_zero<<<Bn, Hn>>>();   // index 2; no dep on gemm

    const int gemm_smem = NSTAGE * STAGE_BYTES;   // 122880
    cudaFuncSetAttribute(gemm_qkv, cudaFuncAttributeMaxDynamicSharedMemorySize, gemm_smem);
    gemm_qkv<<<dim3(Hn / 128, Mn / 128, 3), 256, gemm_smem>>>(bq, bk, bv);  // index 3 (ncu target)

    vsum_part<<<dim3(Bn, CHn), Hn>>>();
    tail_copy<<<Bn * Tn, Hn>>>(out);

    const size_t smem = (size_t)(64 * SKS + 192 * SKS + 192 * SVS + 64 * SPS + 3 * 64) * sizeof(float);
    cudaFuncSetAttribute(attn_kernel, cudaFuncAttributeMaxDynamicSharedMemorySize, (int)smem);
    attn_kernel<<<dim3(CHn, NHn, Bn), 512, smem>>>(out);
}

// round 5
// speedup vs baseline: 1.9968x; 1.1422x over previous
#include <cuda_runtime.h>
#include <cuda_bf16.h>
#include <cstdint>
#include <math.h>

#define Bn 16
#define Sn 768
#define Hn 768
#define Tn 128
#define NQn 640
#define DHn 64
#define NHn 12
#define CHn 10
#define Mn (Bn * Sn)   // 12288

// ---------------- device scratch (no cudaMalloc allowed) -------------------
__device__ float g_Q[(size_t)Mn * Hn];
__device__ float g_K[(size_t)Mn * Hn];
__device__ float g_V[(size_t)Mn * Hn];
__device__ float g_Vsum[Bn * Hn];
__device__ __nv_bfloat16 g_hs_hi[(size_t)Mn * Hn];
__device__ __nv_bfloat16 g_hs_lo[(size_t)Mn * Hn];
__device__ __nv_bfloat16 g_W_hi[3 * Hn * Hn];
__device__ __nv_bfloat16 g_W_lo[3 * Hn * Hn];

// ---------------------------------------------------------------------------
// fp32 -> (bf16 hi, bf16 lo) split conversions (vectorized)
// ---------------------------------------------------------------------------
__global__ void cvt_hs(const float* __restrict__ hs)
{
    const int n4 = (Mn * Hn) / 4;
    __nv_bfloat162* hi2 = (__nv_bfloat162*)g_hs_hi;
    __nv_bfloat162* lo2 = (__nv_bfloat162*)g_hs_lo;
    for (int i = blockIdx.x * blockDim.x + threadIdx.x; i < n4;
         i += gridDim.x * blockDim.x) {
        float4 x = ((const float4*)hs)[i];
        __nv_bfloat16 h0 = __float2bfloat16(x.x), h1 = __float2bfloat16(x.y);
        __nv_bfloat16 h2 = __float2bfloat16(x.z), h3 = __float2bfloat16(x.w);
        hi2[2 * i + 0] = __nv_bfloat162(h0, h1);
        hi2[2 * i + 1] = __nv_bfloat162(h2, h3);
        lo2[2 * i + 0] = __nv_bfloat162(
            __float2bfloat16(x.x - __bfloat162float(h0)),
            __float2bfloat16(x.y - __bfloat162float(h1)));
        lo2[2 * i + 1] = __nv_bfloat162(
            __float2bfloat16(x.z - __bfloat162float(h2)),
            __float2bfloat16(x.w - __bfloat162float(h3)));
    }
}

__global__ void cvt_w(const float* __restrict__ Wq, const float* __restrict__ Wk,
                      const float* __restrict__ Wv)
{
    const int n = Hn * Hn;
    for (int i = blockIdx.x * blockDim.x + threadIdx.x; i < 3 * n;
         i += gridDim.x * blockDim.x) {
        int z = i / n, j = i - z * n;
        const float* W = (z == 0) ? Wq : (z == 1) ? Wk : Wv;
        float x = W[j];
        __nv_bfloat16 hi = __float2bfloat16(x);
        g_W_hi[i] = hi;
        g_W_lo[i] = __float2bfloat16(x - __bfloat162float(hi));
    }
}

// ---------------------------------------------------------------------------
// Compensated bf16 tensor-core GEMM:  C = A @ W^T + bias
// 128x128 tile, BK=32, 256 threads, ldmatrix + 2-stage cp.async, 2 CTAs/SM.
// ---------------------------------------------------------------------------
__device__ __forceinline__ void mma_bf16(float c[4], uint32_t a0, uint32_t a1,
                                         uint32_t a2, uint32_t a3,
                                         uint32_t b0, uint32_t b1)
{
    asm volatile(
        "mma.sync.aligned.m16n8k16.row.col.f32.bf16.bf16.f32 "
        "{%0,%1,%2,%3}, {%4,%5,%6,%7}, {%8,%9}, {%0,%1,%2,%3};\n"
        : "+f"(c[0]), "+f"(c[1]), "+f"(c[2]), "+f"(c[3])
        : "r"(a0), "r"(a1), "r"(a2), "r"(a3), "r"(b0), "r"(b1));
}

__device__ __forceinline__ void ldsm_x4(uint32_t& r0, uint32_t& r1, uint32_t& r2,
                                        uint32_t& r3, uint32_t saddr)
{
    asm volatile("ldmatrix.sync.aligned.m8n8.x4.shared.b16 {%0,%1,%2,%3}, [%4];\n"
                 : "=r"(r0), "=r"(r1), "=r"(r2), "=r"(r3) : "r"(saddr));
}

#define CPASYNC16(saddr, gptr) \
    asm volatile("cp.async.cg.shared.global [%0], [%1], 16;\n" :: "r"(saddr), "l"(gptr))
#define CP_COMMIT() asm volatile("cp.async.commit_group;\n")
#define CP_WAIT(N)  asm volatile("cp.async.wait_group %0;\n" :: "n"(N))

#define TILE_ELEMS (128 * 40)             // bf16 elems per array (32 data + 8 pad/row)
#define STAGE_BYTES (4 * TILE_ELEMS * 2)  // 40960
#define NSTAGE 2

__global__ __launch_bounds__(256, 2) void gemm_qkv(
    const float* __restrict__ bq, const float* __restrict__ bk,
    const float* __restrict__ bv)
{
    extern __shared__ __nv_bfloat16 smem[];

    const int tid = threadIdx.x;
    const int rowBase = blockIdx.y * 128;
    const int colBase = blockIdx.x * 128;
    const int z = blockIdx.z;

    const __nv_bfloat16* Ahi = g_hs_hi + (size_t)rowBase * Hn;
    const __nv_bfloat16* Alo = g_hs_lo + (size_t)rowBase * Hn;
    const __nv_bfloat16* Whi = g_W_hi + (size_t)z * Hn * Hn + (size_t)colBase * Hn;
    const __nv_bfloat16* Wlo = g_W_lo + (size_t)z * Hn * Hn + (size_t)colBase * Hn;
    float* C = (z == 0) ? g_Q : (z == 1) ? g_K : g_V;
    const float* bias = (z == 0) ? bq : (z == 1) ? bk : bv;

    const uint32_t sbase = (uint32_t)__cvta_generic_to_shared(smem);

    const int lrow = tid >> 2;
    const int lkc  = (tid & 3) * 8;

    const int warp  = tid >> 5;
    const int lane  = tid & 31;
    const int warpM = warp >> 2;
    const int warpN = warp & 3;
    const int g  = lane >> 2;
    const int tq = lane & 3;
    const int mrow = warpM * 64;
    const int nrow = warpN * 32;
    const int rsel = lane & 15;
    const int ksel = lane >> 4;
    const uint32_t laneoff = (uint32_t)(rsel * 80 + ksel * 16);

    float acc[4][4][4];
#pragma unroll
    for (int mi = 0; mi < 4; mi++)
#pragma unroll
        for (int ni = 0; ni < 4; ni++)
#pragma unroll
            for (int r = 0; r < 4; r++) acc[mi][ni][r] = 0.f;

    auto load_tiles = [&](int stage, int k0) {
        uint32_t s0 = sbase + stage * STAGE_BYTES;
#pragma unroll
        for (int r2 = 0; r2 < 2; r2++) {
            int r = lrow + r2 * 64;
            uint32_t so = (uint32_t)(r * 80 + lkc * 2);
            size_t go = (size_t)r * Hn + k0 + lkc;
            CPASYNC16(s0 + 0 * (TILE_ELEMS * 2) + so, Ahi + go);
            CPASYNC16(s0 + 1 * (TILE_ELEMS * 2) + so, Alo + go);
            CPASYNC16(s0 + 2 * (TILE_ELEMS * 2) + so, Whi + go);
            CPASYNC16(s0 + 3 * (TILE_ELEMS * 2) + so, Wlo + go);
        }
    };

    auto compute = [&](int stage) {
        uint32_t s0 = sbase + stage * STAGE_BYTES;
        const uint32_t sAhi = s0 + 0 * (TILE_ELEMS * 2) + laneoff;
        const uint32_t sAlo = s0 + 1 * (TILE_ELEMS * 2) + laneoff;
        const uint32_t sWhi = s0 + 2 * (TILE_ELEMS * 2) + laneoff;
        const uint32_t sWlo = s0 + 3 * (TILE_ELEMS * 2) + laneoff;
#pragma unroll
        for (int ks = 0; ks < 2; ks++) {
            const uint32_t ko = (uint32_t)(ks * 32);
            uint32_t ahi[4][4], bhi[4][2];
#pragma unroll
            for (int nj = 0; nj < 2; nj++) {
                uint32_t r0, r1, r2, r3;
                ldsm_x4(r0, r1, r2, r3, sWhi + (uint32_t)((nrow + nj * 16) * 80) + ko);
                bhi[nj * 2 + 0][0] = r0; bhi[nj * 2 + 1][0] = r1;
                bhi[nj * 2 + 0][1] = r2; bhi[nj * 2 + 1][1] = r3;
            }
#pragma unroll
            for (int mi = 0; mi < 4; mi++)
                ldsm_x4(ahi[mi][0], ahi[mi][1], ahi[mi][2], ahi[mi][3],
                        sAhi + (uint32_t)((mrow + mi * 16) * 80) + ko);
#pragma unroll
            for (int mi = 0; mi < 4; mi++)
#pragma unroll
                for (int ni = 0; ni < 4; ni++)
                    mma_bf16(acc[mi][ni], ahi[mi][0], ahi[mi][1], ahi[mi][2],
                             ahi[mi][3], bhi[ni][0], bhi[ni][1]);
            {
                uint32_t blo[4][2];
#pragma unroll
                for (int nj = 0; nj < 2; nj++) {
                    uint32_t r0, r1, r2, r3;
                    ldsm_x4(r0, r1, r2, r3, sWlo + (uint32_t)((nrow + nj * 16) * 80) + ko);
                    blo[nj * 2 + 0][0] = r0; blo[nj * 2 + 1][0] = r1;
                    blo[nj * 2 + 0][1] = r2; blo[nj * 2 + 1][1] = r3;
                }
#pragma unroll
                for (int mi = 0; mi < 4; mi++)
#pragma unroll
                    for (int ni = 0; ni < 4; ni++)
                        mma_bf16(acc[mi][ni], ahi[mi][0], ahi[mi][1], ahi[mi][2],
                                 ahi[mi][3], blo[ni][0], blo[ni][1]);
            }
            {
                uint32_t alo[4][4];
#pragma unroll
                for (int mi = 0; mi < 4; mi++)
                    ldsm_x4(alo[mi][0], alo[mi][1], alo[mi][2], alo[mi][3],
                            sAlo + (uint32_t)((mrow + mi * 16) * 80) + ko);
#pragma unroll
                for (int mi = 0; mi < 4; mi++)
#pragma unroll
                    for (int ni = 0; ni < 4; ni++)
                        mma_bf16(acc[mi][ni], alo[mi][0], alo[mi][1], alo[mi][2],
                                 alo[mi][3], bhi[ni][0], bhi[ni][1]);
            }
        }
    };

    const int NKT = Hn / 32;   // 24
    load_tiles(0, 0);
    CP_COMMIT();

    for (int kt = 0; kt < NKT; kt++) {
        CP_WAIT(0);
        __syncthreads();
        if (kt + 1 < NKT) {
            load_tiles((kt + 1) & 1, (kt + 1) * 32);
            CP_COMMIT();
        }
        compute(kt & 1);
    }

#pragma unroll
    for (int mi = 0; mi < 4; mi++) {
#pragma unroll
        for (int ni = 0; ni < 4; ni++) {
            int row0 = rowBase + mrow + mi * 16 + g;
            int col0 = colBase + nrow + ni * 8 + 2 * tq;
            float b0 = bias[col0], b1 = bias[col0 + 1];
            float2 v0 = make_float2(acc[mi][ni][0] + b0, acc[mi][ni][1] + b1);
            float2 v1 = make_float2(acc[mi][ni][2] + b0, acc[mi][ni][3] + b1);
            *(float2*)(C + (size_t)row0 * Hn + col0) = v0;
            *(float2*)(C + (size_t)(row0 + 8) * Hn + col0) = v1;
        }
    }
}

// ---------------------------------------------------------------------------
__global__ void vsum_zero()
{
    g_Vsum[blockIdx.x * Hn + threadIdx.x] = 0.f;
}

__global__ void vsum_part()
{
    int b = blockIdx.x, c = blockIdx.y;
    int col = threadIdx.x;
    const float* base = g_V + ((size_t)b * Sn + c * 64) * Hn + col;
    float acc = 0.f;
#pragma unroll 8
    for (int s = 0; s < 64; s++) acc += base[(size_t)s * Hn];
    atomicAdd(&g_Vsum[b * Hn + col], acc);
}

__global__ void tail_copy(float* __restrict__ out)
{
    int b = blockIdx.x / Tn;
    int t = blockIdx.x % Tn;
    size_t r = (size_t)b * Sn + NQn + t;
    out[r * Hn + threadIdx.x] = g_V[r * Hn + threadIdx.x];
}

// ---------------------------------------------------------------------------
// Fused attention (512 threads, 2 CTAs/SM): one CTA per (chunk, head, batch).
// smem: sq(64x68) + sk(192x68); sp(64x193) overlays sq/sk after score phase.
// V is read straight from L1/L2 via __ldg float4 (no smem tile).
// ---------------------------------------------------------------------------
#define SQS 68
#define SPS 193
#define SMALL_OFF (64 * SQS + 192 * SQS)   // 17408 floats

__global__ __launch_bounds__(512, 2) void attn_kernel(float* __restrict__ out)
{
    extern __shared__ float sm[];
    float* sq  = sm;                    // 64 * 68
    float* sk  = sm + 64 * SQS;         // 192 * 68
    float* sp  = sm;                    // overlay (64*193 <= 17408)
    float* sem = sm + SMALL_OFF;        // 64
    float* sz  = sem + 64;              // 64
    float* sms = sz + 64;               // 64

    const int tid = threadIdx.x;
    const int chunk = blockIdx.x;
    const int h = blockIdx.y;
    const int b = blockIdx.z;

    const size_t baseC = ((size_t)b * Sn + chunk * 64) * Hn + h * DHn;
    const size_t baseT = ((size_t)b * Sn + 576) * Hn + h * DHn;   // rows 576+j, j>=64
    const float* vc = g_V + baseC;
    const float* vt = g_V + ((size_t)b * Sn + NQn) * Hn + h * DHn;

    for (int idx = tid; idx < 64 * 64; idx += 512) {
        int i = idx >> 6, d = idx & 63;
        sq[i * SQS + d] = g_Q[baseC + (size_t)i * Hn + d];
    }
    for (int idx = tid; idx < 192 * 64; idx += 512) {
        int j = idx >> 6, d = idx & 63;
        size_t off = (j < 64) ? (baseC + (size_t)j * Hn + d)
                              : (baseT + (size_t)j * Hn + d);
        sk[j * SQS + d] = g_K[off];
    }
    __syncthreads();

    const int tx = tid & 15;
    const int ty = tid >> 4;      // 0..31
    const int i0 = ty * 2;

    // scores in registers: 2 rows x 12 interleaved cols (j = tx + 16*jj)
    float acc[2][12];
#pragma unroll
    for (int ii = 0; ii < 2; ii++)
#pragma unroll
        for (int jj = 0; jj < 12; jj++) acc[ii][jj] = 0.f;

    for (int d4 = 0; d4 < 16; d4++) {
        float4 a0 = *(const float4*)&sq[i0 * SQS + d4 * 4];
        float4 a1 = *(const float4*)&sq[(i0 + 1) * SQS + d4 * 4];
#pragma unroll
        for (int grp = 0; grp < 3; grp++) {
            float4 kb[4];
#pragma unroll
            for (int u = 0; u < 4; u++)
                kb[u] = *(const float4*)&sk[(tx + 16 * (grp * 4 + u)) * SQS + d4 * 4];
#pragma unroll
            for (int u = 0; u < 4; u++) {
                int jj = grp * 4 + u;
                acc[0][jj] = fmaf(a0.x, kb[u].x, acc[0][jj]);
                acc[0][jj] = fmaf(a0.y, kb[u].y, acc[0][jj]);
                acc[0][jj] = fmaf(a0.z, kb[u].z, acc[0][jj]);
                acc[0][jj] = fmaf(a0.w, kb[u].w, acc[0][jj]);
                acc[1][jj] = fmaf(a1.x, kb[u].x, acc[1][jj]);
                acc[1][jj] = fmaf(a1.y, kb[u].y, acc[1][jj]);
                acc[1][jj] = fmaf(a1.z, kb[u].z, acc[1][jj]);
                acc[1][jj] = fmaf(a1.w, kb[u].w, acc[1][jj]);
            }
        }
    }
    __syncthreads();   // all sq/sk reads done -> safe to overlay sp

#pragma unroll
    for (int ii = 0; ii < 2; ii++)
#pragma unroll
        for (int jj = 0; jj < 12; jj++)
            sp[(i0 + ii) * SPS + tx + 16 * jj] = acc[ii][jj] * 0.125f;

    // masked-v sum: d = tid/8, 8 threads sum 8 chunk-rows each (global reads)
    {
        const int d = tid >> 3, part = tid & 7;
        float s = 0.f;
#pragma unroll
        for (int j = part * 8; j < part * 8 + 8; j++)
            s += __ldg(vc + (size_t)j * Hn + d);
        s += __shfl_xor_sync(0xFFFFFFFFu, s, 1);
        s += __shfl_xor_sync(0xFFFFFFFFu, s, 2);
        s += __shfl_xor_sync(0xFFFFFFFFu, s, 4);
        if (part == 0) sms[d] = __ldg(&g_Vsum[b * Hn + h * DHn + d]) - s;
    }
    __syncthreads();

    // softmax: row = tid/8, 8 threads x 24 cols; masked cols add 576*exp(-m)
    {
        const int i = tid >> 3, part = tid & 7;
        const int j0 = part * 24;
        float m = 0.f;   // masked scores are exactly 0
#pragma unroll
        for (int j = j0; j < j0 + 24; j++) m = fmaxf(m, sp[i * SPS + j]);
        m = fmaxf(m, __shfl_xor_sync(0xFFFFFFFFu, m, 1));
        m = fmaxf(m, __shfl_xor_sync(0xFFFFFFFFu, m, 2));
        m = fmaxf(m, __shfl_xor_sync(0xFFFFFFFFu, m, 4));
        float Z = 0.f;
#pragma unroll
        for (int j = j0; j < j0 + 24; j++) {
            float e = __expf(sp[i * SPS + j] - m);
            sp[i * SPS + j] = e;
            Z += e;
        }
        Z += __shfl_xor_sync(0xFFFFFFFFu, Z, 1);
        Z += __shfl_xor_sync(0xFFFFFFFFu, Z, 2);
        Z += __shfl_xor_sync(0xFFFFFFFFu, Z, 4);
        if (part == 0) {
            float em = __expf(-m);
            sem[i] = em;
            sz[i] = 1.f / (Z + 576.f * em);
        }
    }
    __syncthreads();

    // ctx: 2 rows x 4 cols per thread; V via __ldg (L1/L2 resident)
    {
        float o[2][4];
#pragma unroll
        for (int ii = 0; ii < 2; ii++)
#pragma unroll
            for (int dd = 0; dd < 4; dd++) o[ii][dd] = 0.f;
        const int d0 = tx * 4;
        for (int j = 0; j < 64; j++) {
            float p0 = sp[i0 * SPS + j];
            float p1 = sp[(i0 + 1) * SPS + j];
            float4 vj = __ldg((const float4*)(vc + (size_t)j * Hn + d0));
            o[0][0] = fmaf(p0, vj.x, o[0][0]);
            o[0][1] = fmaf(p0, vj.y, o[0][1]);
            o[0][2] = fmaf(p0, vj.z, o[0][2]);
            o[0][3] = fmaf(p0, vj.w, o[0][3]);
            o[1][0] = fmaf(p1, vj.x, o[1][0]);
            o[1][1] = fmaf(p1, vj.y, o[1][1]);
            o[1][2] = fmaf(p1, vj.z, o[1][2]);
            o[1][3] = fmaf(p1, vj.w, o[1][3]);
        }
        for (int j = 0; j < 128; j++) {
            float p0 = sp[i0 * SPS + 64 + j];
            float p1 = sp[(i0 + 1) * SPS + 64 + j];
            float4 vj = __ldg((const float4*)(vt + (size_t)j * Hn + d0));
            o[0][0] = fmaf(p0, vj.x, o[0][0]);
            o[0][1] = fmaf(p0, vj.y, o[0][1]);
            o[0][2] = fmaf(p0, vj.z, o[0][2]);
            o[0][3] = fmaf(p0, vj.w, o[0][3]);
            o[1][0] = fmaf(p1, vj.x, o[1][0]);
            o[1][1] = fmaf(p1, vj.y, o[1][1]);
            o[1][2] = fmaf(p1, vj.z, o[1][2]);
            o[1][3] = fmaf(p1, vj.w, o[1][3]);
        }
#pragma unroll
        for (int ii = 0; ii < 2; ii++) {
            float inv = sz[i0 + ii];
            float em  = sem[i0 + ii];
            float4 ov;
            ov.x = (o[ii][0] + em * sms[d0 + 0]) * inv;
            ov.y = (o[ii][1] + em * sms[d0 + 1]) * inv;
            ov.z = (o[ii][2] + em * sms[d0 + 2]) * inv;
            ov.w = (o[ii][3] + em * sms[d0 + 3]) * inv;
            *(float4*)(out + ((size_t)b * Sn + chunk * 64 + i0 + ii) * Hn + h * DHn + d0) = ov;
        }
    }
}

// ---------------------------------------------------------------------------
extern "C" void kernel_launch(void* const* d_in, const int* in_sizes, int n_in,
                              void* d_out, int out_size)
{
    const float* hs = (const float*)d_in[0];
    const float* Wq = (const float*)d_in[1];
    const float* bq = (const float*)d_in[2];
    const float* Wk = (const float*)d_in[3];
    const float* bk = (const float*)d_in[4];
    const float* Wv = (const float*)d_in[5];
    const float* bv = (const float*)d_in[6];
    float* out = (float*)d_out;

    cvt_hs<<<2048, 256>>>(hs);
    cvt_w<<<2048, 256>>>(Wq, Wk, Wv);
    vsum_zero<<<Bn, Hn>>>();

    const int gemm_smem = NSTAGE * STAGE_BYTES;   // 81920
    cudaFuncSetAttribute(gemm_qkv, cudaFuncAttributeMaxDynamicSharedMemorySize, gemm_smem);
    gemm_qkv<<<dim3(Hn / 128, Mn / 128, 3), 256, gemm_smem>>>(bq, bk, bv);  // idx 3 (ncu)

    vsum_part<<<dim3(Bn, CHn), Hn>>>();
    tail_copy<<<Bn * Tn, Hn>>>(out);

    const size_t attn_smem = (size_t)(SMALL_OFF + 3 * 64) * sizeof(float);  // 70400 B
    cudaFuncSetAttribute(attn_kernel, cudaFuncAttributeMaxDynamicSharedMemorySize, (int)attn_smem);
    attn_kernel<<<dim3(CHn, NHn, Bn), 512, attn_smem>>>(out);
}